// round 11
// baseline (speedup 1.0000x reference)
#include <cuda_runtime.h>
#include <cuda.h>
#include <cstdint>

#define T_DIM 8192
#define D_DIM 5120
#define H_DIM 13824

#define BM 128
#define BN 256          // 128 tensor cols + 128 dp4a cols
#define BK 128          // 128-byte K chunk (SW128 native)
#define A_BYTES (128 * 128)               // 16384
#define B_BYTES (256 * 128)               // 32768
#define STAGE_BYTES (A_BYTES + B_BYTES)   // 49152
#define STAGES 3
#define SMEM_CTRL 1024
#define SMEM_BYTES (SMEM_CTRL + STAGES * STAGE_BYTES)  // 148480

// ---------------- scratch (device globals: allocation-free rule) --------------
__device__ uint8_t d_w1u8[(size_t)H_DIM * D_DIM];
__device__ uint8_t d_w2u8[(size_t)D_DIM * H_DIM];
__device__ int8_t  d_q1[(size_t)T_DIM * D_DIM];
__device__ int8_t  d_q2[(size_t)T_DIM * H_DIM];
__device__ float   d_g [(size_t)T_DIM * H_DIM];
__device__ float   d_s1[T_DIM];
__device__ int     d_sum1[T_DIM];
__device__ float   d_s2[T_DIM];
__device__ int     d_sum2[T_DIM];

// ---------------- helpers ------------------------------------------------------
__device__ __forceinline__ uint32_t smem_u32(const void* p) {
    uint32_t a;
    asm("{ .reg .u64 t; cvta.to.shared.u64 t, %1; cvt.u32.u64 %0, t; }" : "=r"(a) : "l"(p));
    return a;
}

#define MBARRIER_INIT(mbar, count) \
    asm volatile("mbarrier.init.shared.b64 [%0], %1;" \
        :: "r"((uint32_t)(mbar)), "r"((uint32_t)(count)) : "memory")

#define MBARRIER_EXPECT_TX(mbar, tx) \
    asm volatile("mbarrier.arrive.expect_tx.shared.b64 _, [%0], %1;" \
        :: "r"((uint32_t)(mbar)), "r"((uint32_t)(tx)) : "memory")

#define MBARRIER_WAIT_PARITY(mbar, parity) do { \
    uint32_t _m = (uint32_t)(mbar), _p = (uint32_t)(parity), _d; \
    asm volatile("{\n\t.reg .pred p;\n\t" \
        "mbarrier.try_wait.parity.acquire.cta.shared::cta.b64 p, [%1], %2;\n\t" \
        "selp.b32 %0, 1, 0, p;\n\t}" : "=r"(_d) : "r"(_m), "r"(_p) : "memory"); \
    if (!_d) { \
        asm volatile("{\n\t.reg .pred P1;\n\t" \
            "WL_%=:\n\t" \
            "mbarrier.try_wait.parity.acquire.cta.shared::cta.b64 P1, [%0], %1, 0x989680;\n\t" \
            "@P1 bra.uni WD_%=;\n\t" \
            "bra.uni WL_%=;\n\t" \
            "WD_%=:\n\t}" :: "r"(_m), "r"(_p) : "memory"); \
    } \
} while(0)

__device__ __forceinline__ void tma2d(uint32_t dst, const void* map, int x, int y, uint32_t bar) {
    asm volatile(
        "cp.async.bulk.tensor.2d.shared::cta.global.tile.mbarrier::complete_tx::bytes "
        "[%0], [%1, {%2, %3}], [%4];"
        :: "r"(dst), "l"(map), "r"(x), "r"(y), "r"(bar) : "memory");
}

__device__ __forceinline__ void mma_s8u8(int* c, const int* a, const int* b) {
    asm volatile(
        "mma.sync.aligned.m16n8k32.row.col.s32.s8.u8.s32 "
        "{%0,%1,%2,%3}, {%4,%5,%6,%7}, {%8,%9}, {%0,%1,%2,%3};\n"
        : "+r"(c[0]), "+r"(c[1]), "+r"(c[2]), "+r"(c[3])
        : "r"(a[0]), "r"(a[1]), "r"(a[2]), "r"(a[3]), "r"(b[0]), "r"(b[1]));
}

__device__ __forceinline__ int dp4a_su(int a, int b, int c) {
    int d;
    asm("dp4a.s32.u32 %0, %1, %2, %3;" : "=r"(d) : "r"(a), "r"(b), "r"(c));
    return d;
}

__device__ __forceinline__ float gelu_exact(float v) {
    return v * (erff(__fdiv_rn(v, 1.41421356237309515f)) + 1.0f) * 0.5f;
}

// TMA SW128 layout: row r (128B pitch), 16B chunk c stored at chunk (c ^ (r&7))
__device__ __forceinline__ uint32_t swoff(int row, int chunk) {
    return (uint32_t)((row << 7) + (((chunk ^ row) & 7) << 4));
}

// ---------------- weight pack: int32 code [0,255] -> u8 raw -------------------
__global__ void convert_weights(const int* __restrict__ w, uint8_t* __restrict__ o, int n4) {
    int i = blockIdx.x * blockDim.x + threadIdx.x;
    if (i < n4) {
        int4 v = ((const int4*)w)[i];
        unsigned p = (unsigned)(v.x & 0xff)
                   | ((unsigned)(v.y & 0xff) << 8)
                   | ((unsigned)(v.z & 0xff) << 16)
                   | ((unsigned)(v.w & 0xff) << 24);
        ((unsigned*)o)[i] = p;
    }
}

// ---------------- per-row dynamic int8 quant ----------------------------------
template<int THREADS, int V>
__global__ void quant_rows(const float* __restrict__ x, int8_t* __restrict__ q,
                           float* __restrict__ s_out, int* __restrict__ sum_out,
                           int cols) {
    constexpr int NW = THREADS / 32;
    __shared__ float smax[NW];
    __shared__ int   ssum[NW];
    int row  = blockIdx.x;
    int tid  = threadIdx.x;
    int lane = tid & 31, w = tid >> 5;

    const float4* xr = (const float4*)(x + (size_t)row * cols);
    float4 v[V];
    float m = 0.0f;
#pragma unroll
    for (int i = 0; i < V; i++) {
        v[i] = xr[i * THREADS + tid];
        m = fmaxf(m, fmaxf(fmaxf(fabsf(v[i].x), fabsf(v[i].y)),
                           fmaxf(fabsf(v[i].z), fabsf(v[i].w))));
    }
#pragma unroll
    for (int o = 16; o; o >>= 1) m = fmaxf(m, __shfl_xor_sync(0xffffffffu, m, o));
    if (lane == 0) smax[w] = m;
    __syncthreads();
    if (tid == 0) {
        float mm = smax[0];
#pragma unroll
        for (int i = 1; i < NW; i++) mm = fmaxf(mm, smax[i]);
        smax[0] = mm;
    }
    __syncthreads();
    m = smax[0];

    float s = fmaxf(__fdiv_rn(m, 127.0f), 1e-8f);

    unsigned* qo = (unsigned*)(q + (size_t)row * cols);
    int isum = 0;
#pragma unroll
    for (int i = 0; i < V; i++) {
        float fs[4] = {v[i].x, v[i].y, v[i].z, v[i].w};
        int qi[4];
#pragma unroll
        for (int c = 0; c < 4; c++) {
            float r = rintf(__fdiv_rn(fs[c], s));
            r = fminf(fmaxf(r, -127.0f), 127.0f);
            qi[c] = (int)r;
            isum += qi[c];
        }
        unsigned p = (unsigned)(qi[0] & 0xff)
                   | ((unsigned)(qi[1] & 0xff) << 8)
                   | ((unsigned)(qi[2] & 0xff) << 16)
                   | ((unsigned)(qi[3] & 0xff) << 24);
        qo[i * THREADS + tid] = p;
    }
#pragma unroll
    for (int o = 16; o; o >>= 1) isum += __shfl_xor_sync(0xffffffffu, isum, o);
    if (lane == 0) ssum[w] = isum;
    __syncthreads();
    if (tid == 0) {
        int t = 0;
#pragma unroll
        for (int i = 0; i < NW; i++) t += ssum[i];
        sum_out[row] = t;
        s_out[row]   = s;
    }
}

// ===== TMA-fed hybrid GEMM: tensor (cols 0..127) + dp4a (cols 128..255) =======
template<bool DO_GELU>
__global__ __launch_bounds__(512, 1)
void gemm_hybrid(const __grid_constant__ CUtensorMap ta,
                 const __grid_constant__ CUtensorMap tb,
                 float* __restrict__ C, int K, int N,
                 const float* __restrict__ sA, const int* __restrict__ sumA,
                 const float* __restrict__ sW, const float* __restrict__ zp,
                 const float* __restrict__ bias) {
    extern __shared__ int8_t smem[];
    uint32_t smu = smem_u32(smem);

    int tid = threadIdx.x;
    int bm = blockIdx.y * BM, bn = blockIdx.x * BN;
    int KT = K >> 7;                      // BK = 128

    int lane = tid & 31, wid = tid >> 5;
    // tensor role: warps 8-15, 2 warpM x 4 warpN over cols 0..127
    int tw = wid - 8;
    int warpM = tw >> 2, warpN = tw & 3;
    int arowL = warpM * 64 + (lane >> 2);
    int browL = warpN * 32 + (lane >> 2);
    int koff  = (lane & 3) * 4;
    // dp4a role: warps 0-7, 256 threads 16x16; rows 8*tRow..+8, cols 128+16j+tCol
    int tRow = tid >> 4, tCol = tid & 15;

    // mbarriers: full[s] at smu + 16 + 8*s
    if (tid == 0) {
#pragma unroll
        for (int s = 0; s < STAGES; s++)
            MBARRIER_INIT(smu + 16 + 8 * s, 1);
        asm volatile("fence.mbarrier_init.release.cluster;" ::: "memory");
        asm volatile("fence.proxy.async.shared::cta;" ::: "memory");
    }
    __syncthreads();

    // prefill all 3 stages
    if (tid == 0) {
        asm volatile("prefetch.tensormap [%0];" :: "l"(&ta));
        asm volatile("prefetch.tensormap [%0];" :: "l"(&tb));
#pragma unroll
        for (int s = 0; s < STAGES; s++) {
            if (s < KT) {
                uint32_t bar = smu + 16 + 8 * s;
                uint32_t ab  = smu + SMEM_CTRL + s * STAGE_BYTES;
                MBARRIER_EXPECT_TX(bar, (uint32_t)STAGE_BYTES);
                tma2d(ab,                      &ta, s * BK, bm,       bar);
                tma2d(ab + A_BYTES,            &tb, s * BK, bn,       bar);
                tma2d(ab + A_BYTES + 16384,    &tb, s * BK, bn + 128, bar);
            }
        }
    }

    int acc[64];
#pragma unroll
    for (int i = 0; i < 64; i++) acc[i] = 0;

    for (int kt = 0; kt < KT; kt++) {
        int s = kt % STAGES;
        uint32_t bar = smu + 16 + 8 * s;
        MBARRIER_WAIT_PARITY(bar, (uint32_t)((kt / STAGES) & 1));

        const int8_t* Asb = smem + SMEM_CTRL + s * STAGE_BYTES;
        const int8_t* Bsb = Asb + A_BYTES;

        if (wid >= 8) {                   // ---- tensor warps ----
#pragma unroll
            for (int ks = 0; ks < 4; ks++) {
                int a[4][4], b[4][2];
                int cc0 = ks * 2, cc1 = cc0 + 1;
#pragma unroll
                for (int mi = 0; mi < 4; mi++) {
                    int ra = arowL + mi * 16, rb = ra + 8;
                    a[mi][0] = *(const int*)(Asb + swoff(ra, cc0) + koff);
                    a[mi][1] = *(const int*)(Asb + swoff(rb, cc0) + koff);
                    a[mi][2] = *(const int*)(Asb + swoff(ra, cc1) + koff);
                    a[mi][3] = *(const int*)(Asb + swoff(rb, cc1) + koff);
                }
#pragma unroll
                for (int ni = 0; ni < 4; ni++) {
                    int rb = browL + ni * 8;
                    b[ni][0] = *(const int*)(Bsb + swoff(rb, cc0) + koff);
                    b[ni][1] = *(const int*)(Bsb + swoff(rb, cc1) + koff);
                }
#pragma unroll
                for (int mi = 0; mi < 4; mi++)
#pragma unroll
                    for (int ni = 0; ni < 4; ni++)
                        mma_s8u8(&acc[(mi * 4 + ni) * 4], a[mi], b[ni]);
            }
        } else {                          // ---- dp4a warps ----
#pragma unroll
            for (int cc8 = 0; cc8 < 8; cc8++) {
                int c = (cc8 + tCol) & 7;         // rotation (spread)
                int4 a4[8];
#pragma unroll
                for (int i = 0; i < 8; i++)
                    a4[i] = *(const int4*)(Asb + swoff(tRow * 8 + i, c));
#pragma unroll
                for (int j = 0; j < 8; j++) {
                    int4 b4 = *(const int4*)(Bsb + swoff(128 + j * 16 + tCol, c));
                    const int* bw = (const int*)&b4;
#pragma unroll
                    for (int w = 0; w < 4; w++)
#pragma unroll
                        for (int i = 0; i < 8; i++)
                            acc[i * 8 + j] = dp4a_su(((const int*)&a4[i])[w], bw[w], acc[i * 8 + j]);
                }
            }
        }

        __syncthreads();                  // all consumers done with stage s
        if (tid == 0 && kt + STAGES < KT) {
            uint32_t ab = smu + SMEM_CTRL + s * STAGE_BYTES;
            MBARRIER_EXPECT_TX(bar, (uint32_t)STAGE_BYTES);
            tma2d(ab,                   &ta, (kt + STAGES) * BK, bm,       bar);
            tma2d(ab + A_BYTES,         &tb, (kt + STAGES) * BK, bn,       bar);
            tma2d(ab + A_BYTES + 16384, &tb, (kt + STAGES) * BK, bn + 128, bar);
        }
    }

    // ---- epilogues: dequant (+GELU); BN=256 divides N -> no guards ----
    if (wid >= 8) {                       // tensor cols 0..127
#pragma unroll
        for (int mi = 0; mi < 4; mi++) {
#pragma unroll
            for (int half = 0; half < 2; half++) {
                int r = bm + warpM * 64 + mi * 16 + (lane >> 2) + half * 8;
                float sa   = __ldg(&sA[r]);
                float fsum = (float)__ldg(&sumA[r]);
                float* Crow = C + (size_t)r * N;
#pragma unroll
                for (int ni = 0; ni < 4; ni++) {
                    int cc = bn + warpN * 32 + ni * 8 + (lane & 3) * 2;
                    float f0 = (float)acc[(mi * 4 + ni) * 4 + half * 2 + 0];
                    float f1 = (float)acc[(mi * 4 + ni) * 4 + half * 2 + 1];
                    float v0 = (sa * __ldg(&sW[cc]))     * (f0 - __ldg(&zp[cc])     * fsum) + __ldg(&bias[cc]);
                    float v1 = (sa * __ldg(&sW[cc + 1])) * (f1 - __ldg(&zp[cc + 1]) * fsum) + __ldg(&bias[cc + 1]);
                    if (DO_GELU) { v0 = gelu_exact(v0); v1 = gelu_exact(v1); }
                    *(float2*)(Crow + cc) = make_float2(v0, v1);
                }
            }
        }
    } else {                              // dp4a cols 128..255
#pragma unroll
        for (int i = 0; i < 8; i++) {
            int r = bm + tRow * 8 + i;
            float sa   = __ldg(&sA[r]);
            float fsum = (float)__ldg(&sumA[r]);
            float* Crow = C + (size_t)r * N;
#pragma unroll
            for (int j = 0; j < 8; j++) {
                int cc = bn + 128 + j * 16 + tCol;
                float f = (float)acc[i * 8 + j];
                float v = (sa * __ldg(&sW[cc])) * (f - __ldg(&zp[cc]) * fsum) + __ldg(&bias[cc]);
                if (DO_GELU) v = gelu_exact(v);
                Crow[cc] = v;
            }
        }
    }
}

// ---------------- host: tensormap encode via driver entry point ---------------
typedef CUresult (*PFN_encodeTiled)(
    CUtensorMap*, CUtensorMapDataType, cuuint32_t, void*,
    const cuuint64_t*, const cuuint64_t*, const cuuint32_t*, const cuuint32_t*,
    CUtensorMapInterleave, CUtensorMapSwizzle, CUtensorMapL2promotion,
    CUtensorMapFloatOOBfill);

static void make_map_u8(PFN_encodeTiled enc, CUtensorMap* m, const void* ptr,
                        uint64_t rows, uint64_t cols) {
    cuuint64_t dims[2]    = {cols, rows};
    cuuint64_t strides[1] = {cols};
    cuuint32_t box[2]     = {128, 128};
    cuuint32_t es[2]      = {1, 1};
    enc(m, CU_TENSOR_MAP_DATA_TYPE_UINT8, 2, (void*)ptr, dims, strides, box, es,
        CU_TENSOR_MAP_INTERLEAVE_NONE, CU_TENSOR_MAP_SWIZZLE_128B,
        CU_TENSOR_MAP_L2_PROMOTION_L2_128B, CU_TENSOR_MAP_FLOAT_OOB_FILL_NONE);
}

extern "C" void kernel_launch(void* const* d_in, const int* in_sizes, int n_in,
                              void* d_out, int out_size) {
    const float* x    = (const float*)d_in[0];
    const int*   w1q  = (const int*)  d_in[1];
    const float* w1s  = (const float*)d_in[2];
    const float* w1zp = (const float*)d_in[3];
    const float* b1   = (const float*)d_in[4];
    const int*   w2q  = (const int*)  d_in[5];
    const float* w2s  = (const float*)d_in[6];
    const float* w2zp = (const float*)d_in[7];
    const float* b2   = (const float*)d_in[8];
    float* out = (float*)d_out;

    uint8_t *w1u8, *w2u8;
    int8_t *q1, *q2;
    float *g, *s1, *s2;
    int *sum1, *sum2;
    cudaGetSymbolAddress((void**)&w1u8, d_w1u8);
    cudaGetSymbolAddress((void**)&w2u8, d_w2u8);
    cudaGetSymbolAddress((void**)&q1,   d_q1);
    cudaGetSymbolAddress((void**)&q2,   d_q2);
    cudaGetSymbolAddress((void**)&g,    d_g);
    cudaGetSymbolAddress((void**)&s1,   d_s1);
    cudaGetSymbolAddress((void**)&s2,   d_s2);
    cudaGetSymbolAddress((void**)&sum1, d_sum1);
    cudaGetSymbolAddress((void**)&sum2, d_sum2);

    void* fn = nullptr;
    cudaDriverEntryPointQueryResult qr;
    cudaGetDriverEntryPointByVersion("cuTensorMapEncodeTiled", &fn, 12000,
                                     cudaEnableDefault, &qr);
    PFN_encodeTiled enc = (PFN_encodeTiled)fn;

    CUtensorMap tA1, tB1, tA2, tB2;
    make_map_u8(enc, &tA1, q1,   T_DIM, D_DIM);
    make_map_u8(enc, &tB1, w1u8, H_DIM, D_DIM);
    make_map_u8(enc, &tA2, q2,   T_DIM, H_DIM);
    make_map_u8(enc, &tB2, w2u8, D_DIM, H_DIM);

    cudaFuncSetAttribute(gemm_hybrid<true>,
                         cudaFuncAttributeMaxDynamicSharedMemorySize, SMEM_BYTES);
    cudaFuncSetAttribute(gemm_hybrid<false>,
                         cudaFuncAttributeMaxDynamicSharedMemorySize, SMEM_BYTES);

    const int n4 = (int)(((size_t)H_DIM * D_DIM) / 4);
    convert_weights<<<(n4 + 255) / 256, 256>>>(w1q, w1u8, n4);
    convert_weights<<<(n4 + 255) / 256, 256>>>(w2q, w2u8, n4);

    quant_rows<320, 4><<<T_DIM, 320>>>(x, q1, s1, sum1, D_DIM);

    dim3 g1(H_DIM / BN, T_DIM / BM);             // 54 x 64
    gemm_hybrid<true><<<g1, 512, SMEM_BYTES>>>(tA1, tB1, g, D_DIM, H_DIM,
                                               s1, sum1, w1s, w1zp, b1);

    quant_rows<384, 9><<<T_DIM, 384>>>(g, q2, s2, sum2, H_DIM);

    dim3 g2(D_DIM / BN, T_DIM / BM);             // 20 x 64
    gemm_hybrid<false><<<g2, 512, SMEM_BYTES>>>(tA2, tB2, out, H_DIM, D_DIM,
                                                s2, sum2, w2s, w2zp, b2);
}

// round 12
// speedup vs baseline: 1.3391x; 1.3391x over previous
#include <cuda_runtime.h>
#include <cuda.h>
#include <cstdint>

#define T_DIM 8192
#define D_DIM 5120
#define H_DIM 13824

#define BM 128
#define BN 256          // 128 tensor cols + 128 dp4a cols
#define BK 128          // 128-byte K chunk (SW128 native)
#define A_BYTES (128 * 128)               // 16384
#define B_BYTES (256 * 128)               // 32768
#define STAGE_BYTES (A_BYTES + B_BYTES)   // 49152
#define STAGES 3
#define SMEM_CTRL 1024
#define SMEM_BYTES (SMEM_CTRL + STAGES * STAGE_BYTES)  // 148480

// ---------------- scratch (device globals: allocation-free rule) --------------
__device__ uint8_t d_w1u8[(size_t)H_DIM * D_DIM];
__device__ uint8_t d_w2u8[(size_t)D_DIM * H_DIM];
__device__ int8_t  d_q1[(size_t)T_DIM * D_DIM];
__device__ int8_t  d_q2[(size_t)T_DIM * H_DIM];
__device__ float   d_g [(size_t)T_DIM * H_DIM];
__device__ float   d_s1[T_DIM];
__device__ int     d_sum1[T_DIM];
__device__ float   d_s2[T_DIM];
__device__ int     d_sum2[T_DIM];

// ---------------- helpers ------------------------------------------------------
__device__ __forceinline__ uint32_t smem_u32(const void* p) {
    uint32_t a;
    asm("{ .reg .u64 t; cvta.to.shared.u64 t, %1; cvt.u32.u64 %0, t; }" : "=r"(a) : "l"(p));
    return a;
}

#define MBARRIER_INIT(mbar, count) \
    asm volatile("mbarrier.init.shared.b64 [%0], %1;" \
        :: "r"((uint32_t)(mbar)), "r"((uint32_t)(count)) : "memory")

#define MBARRIER_EXPECT_TX(mbar, tx) \
    asm volatile("mbarrier.arrive.expect_tx.shared.b64 _, [%0], %1;" \
        :: "r"((uint32_t)(mbar)), "r"((uint32_t)(tx)) : "memory")

#define MBARRIER_WAIT_PARITY(mbar, parity) do { \
    uint32_t _m = (uint32_t)(mbar), _p = (uint32_t)(parity), _d; \
    asm volatile("{\n\t.reg .pred p;\n\t" \
        "mbarrier.try_wait.parity.acquire.cta.shared::cta.b64 p, [%1], %2;\n\t" \
        "selp.b32 %0, 1, 0, p;\n\t}" : "=r"(_d) : "r"(_m), "r"(_p) : "memory"); \
    if (!_d) { \
        asm volatile("{\n\t.reg .pred P1;\n\t" \
            "WL_%=:\n\t" \
            "mbarrier.try_wait.parity.acquire.cta.shared::cta.b64 P1, [%0], %1, 0x989680;\n\t" \
            "@P1 bra.uni WD_%=;\n\t" \
            "bra.uni WL_%=;\n\t" \
            "WD_%=:\n\t}" :: "r"(_m), "r"(_p) : "memory"); \
    } \
} while(0)

__device__ __forceinline__ void tma2d(uint32_t dst, const void* map, int x, int y, uint32_t bar) {
    asm volatile(
        "cp.async.bulk.tensor.2d.shared::cta.global.tile.mbarrier::complete_tx::bytes "
        "[%0], [%1, {%2, %3}], [%4];"
        :: "r"(dst), "l"(map), "r"(x), "r"(y), "r"(bar) : "memory");
}

__device__ __forceinline__ void mma_s8u8(int* c, const int* a, const int* b) {
    asm volatile(
        "mma.sync.aligned.m16n8k32.row.col.s32.s8.u8.s32 "
        "{%0,%1,%2,%3}, {%4,%5,%6,%7}, {%8,%9}, {%0,%1,%2,%3};\n"
        : "+r"(c[0]), "+r"(c[1]), "+r"(c[2]), "+r"(c[3])
        : "r"(a[0]), "r"(a[1]), "r"(a[2]), "r"(a[3]), "r"(b[0]), "r"(b[1]));
}

__device__ __forceinline__ int dp4a_su(int a, int b, int c) {
    int d;
    asm("dp4a.s32.u32 %0, %1, %2, %3;" : "=r"(d) : "r"(a), "r"(b), "r"(c));
    return d;
}

__device__ __forceinline__ float gelu_exact(float v) {
    return v * (erff(__fdiv_rn(v, 1.41421356237309515f)) + 1.0f) * 0.5f;
}

// TMA SW128 layout: row r (128B pitch), 16B chunk c stored at chunk (c ^ (r&7))
__device__ __forceinline__ uint32_t swoff(int row, int chunk) {
    return (uint32_t)((row << 7) + (((chunk ^ row) & 7) << 4));
}

// ---------------- weight pack: int32 code [0,255] -> u8 raw -------------------
__global__ void convert_weights(const int* __restrict__ w, uint8_t* __restrict__ o, int n4) {
    int i = blockIdx.x * blockDim.x + threadIdx.x;
    if (i < n4) {
        int4 v = ((const int4*)w)[i];
        unsigned p = (unsigned)(v.x & 0xff)
                   | ((unsigned)(v.y & 0xff) << 8)
                   | ((unsigned)(v.z & 0xff) << 16)
                   | ((unsigned)(v.w & 0xff) << 24);
        ((unsigned*)o)[i] = p;
    }
}

// ---------------- per-row dynamic int8 quant ----------------------------------
template<int THREADS, int V>
__global__ void quant_rows(const float* __restrict__ x, int8_t* __restrict__ q,
                           float* __restrict__ s_out, int* __restrict__ sum_out,
                           int cols) {
    constexpr int NW = THREADS / 32;
    __shared__ float smax[NW];
    __shared__ int   ssum[NW];
    int row  = blockIdx.x;
    int tid  = threadIdx.x;
    int lane = tid & 31, w = tid >> 5;

    const float4* xr = (const float4*)(x + (size_t)row * cols);
    float4 v[V];
    float m = 0.0f;
#pragma unroll
    for (int i = 0; i < V; i++) {
        v[i] = xr[i * THREADS + tid];
        m = fmaxf(m, fmaxf(fmaxf(fabsf(v[i].x), fabsf(v[i].y)),
                           fmaxf(fabsf(v[i].z), fabsf(v[i].w))));
    }
#pragma unroll
    for (int o = 16; o; o >>= 1) m = fmaxf(m, __shfl_xor_sync(0xffffffffu, m, o));
    if (lane == 0) smax[w] = m;
    __syncthreads();
    if (tid == 0) {
        float mm = smax[0];
#pragma unroll
        for (int i = 1; i < NW; i++) mm = fmaxf(mm, smax[i]);
        smax[0] = mm;
    }
    __syncthreads();
    m = smax[0];

    float s = fmaxf(__fdiv_rn(m, 127.0f), 1e-8f);

    unsigned* qo = (unsigned*)(q + (size_t)row * cols);
    int isum = 0;
#pragma unroll
    for (int i = 0; i < V; i++) {
        float fs[4] = {v[i].x, v[i].y, v[i].z, v[i].w};
        int qi[4];
#pragma unroll
        for (int c = 0; c < 4; c++) {
            float r = rintf(__fdiv_rn(fs[c], s));
            r = fminf(fmaxf(r, -127.0f), 127.0f);
            qi[c] = (int)r;
            isum += qi[c];
        }
        unsigned p = (unsigned)(qi[0] & 0xff)
                   | ((unsigned)(qi[1] & 0xff) << 8)
                   | ((unsigned)(qi[2] & 0xff) << 16)
                   | ((unsigned)(qi[3] & 0xff) << 24);
        qo[i * THREADS + tid] = p;
    }
#pragma unroll
    for (int o = 16; o; o >>= 1) isum += __shfl_xor_sync(0xffffffffu, isum, o);
    if (lane == 0) ssum[w] = isum;
    __syncthreads();
    if (tid == 0) {
        int t = 0;
#pragma unroll
        for (int i = 0; i < NW; i++) t += ssum[i];
        sum_out[row] = t;
        s_out[row]   = s;
    }
}

// ===== TMA-fed hybrid GEMM: tensor (cols 0..127) + dp4a (cols 128..255) =======
template<bool DO_GELU>
__global__ __launch_bounds__(512, 1)
void gemm_hybrid(const __grid_constant__ CUtensorMap ta,
                 const __grid_constant__ CUtensorMap tb,
                 float* __restrict__ C, int K, int N,
                 const float* __restrict__ sA, const int* __restrict__ sumA,
                 const float* __restrict__ sW, const float* __restrict__ zp,
                 const float* __restrict__ bias) {
    extern __shared__ int8_t smem[];
    uint32_t smu = smem_u32(smem);

    int tid = threadIdx.x;
    int bm = blockIdx.y * BM, bn = blockIdx.x * BN;
    int KT = K >> 7;                      // BK = 128

    int lane = tid & 31, wid = tid >> 5;
    // tensor role: warps 8-15, 2 warpM x 4 warpN over cols 0..127
    int tw = wid - 8;
    int warpM = tw >> 2, warpN = tw & 3;
    int arowL = warpM * 64 + (lane >> 2);
    int browL = warpN * 32 + (lane >> 2);
    int koff  = (lane & 3) * 4;
    // dp4a role: warps 0-7, 256 threads 16x16;
    // rows 8*tRow..+8, cols 128 + tCol*8 + j (8 consecutive) -> bank-safe with
    // TMA swizzle: B row&7 = j (const per step), stored chunk = c^j distinct/tCol
    int tRow = tid >> 4, tCol = tid & 15;

    // mbarriers: full[s] at smu + 16 + 8*s
    if (tid == 0) {
#pragma unroll
        for (int s = 0; s < STAGES; s++)
            MBARRIER_INIT(smu + 16 + 8 * s, 1);
        asm volatile("fence.mbarrier_init.release.cluster;" ::: "memory");
        asm volatile("fence.proxy.async.shared::cta;" ::: "memory");
    }
    __syncthreads();

    // prefill all 3 stages
    if (tid == 0) {
        asm volatile("prefetch.tensormap [%0];" :: "l"(&ta));
        asm volatile("prefetch.tensormap [%0];" :: "l"(&tb));
#pragma unroll
        for (int s = 0; s < STAGES; s++) {
            if (s < KT) {
                uint32_t bar = smu + 16 + 8 * s;
                uint32_t ab  = smu + SMEM_CTRL + s * STAGE_BYTES;
                MBARRIER_EXPECT_TX(bar, (uint32_t)STAGE_BYTES);
                tma2d(ab,                      &ta, s * BK, bm,       bar);
                tma2d(ab + A_BYTES,            &tb, s * BK, bn,       bar);
                tma2d(ab + A_BYTES + 16384,    &tb, s * BK, bn + 128, bar);
            }
        }
    }

    int acc[64];
#pragma unroll
    for (int i = 0; i < 64; i++) acc[i] = 0;

    for (int kt = 0; kt < KT; kt++) {
        int s = kt % STAGES;
        uint32_t bar = smu + 16 + 8 * s;
        MBARRIER_WAIT_PARITY(bar, (uint32_t)((kt / STAGES) & 1));

        const int8_t* Asb = smem + SMEM_CTRL + s * STAGE_BYTES;
        const int8_t* Bsb = Asb + A_BYTES;

        if (wid >= 8) {                   // ---- tensor warps ----
#pragma unroll
            for (int ks = 0; ks < 4; ks++) {
                int a[4][4], b[4][2];
                int cc0 = ks * 2, cc1 = cc0 + 1;
#pragma unroll
                for (int mi = 0; mi < 4; mi++) {
                    int ra = arowL + mi * 16, rb = ra + 8;
                    a[mi][0] = *(const int*)(Asb + swoff(ra, cc0) + koff);
                    a[mi][1] = *(const int*)(Asb + swoff(rb, cc0) + koff);
                    a[mi][2] = *(const int*)(Asb + swoff(ra, cc1) + koff);
                    a[mi][3] = *(const int*)(Asb + swoff(rb, cc1) + koff);
                }
#pragma unroll
                for (int ni = 0; ni < 4; ni++) {
                    int rb = browL + ni * 8;
                    b[ni][0] = *(const int*)(Bsb + swoff(rb, cc0) + koff);
                    b[ni][1] = *(const int*)(Bsb + swoff(rb, cc1) + koff);
                }
#pragma unroll
                for (int mi = 0; mi < 4; mi++)
#pragma unroll
                    for (int ni = 0; ni < 4; ni++)
                        mma_s8u8(&acc[(mi * 4 + ni) * 4], a[mi], b[ni]);
            }
        } else {                          // ---- dp4a warps ----
#pragma unroll
            for (int cc8 = 0; cc8 < 8; cc8++) {
                int c = (cc8 + tCol) & 7;         // rotation (bank spread)
                int4 a4[8];
#pragma unroll
                for (int i = 0; i < 8; i++)
                    a4[i] = *(const int4*)(Asb + swoff(tRow * 8 + i, c));
#pragma unroll
                for (int j = 0; j < 8; j++) {
                    int4 b4 = *(const int4*)(Bsb + swoff(128 + tCol * 8 + j, c));
                    const int* bw = (const int*)&b4;
#pragma unroll
                    for (int w = 0; w < 4; w++)
#pragma unroll
                        for (int i = 0; i < 8; i++)
                            acc[i * 8 + j] = dp4a_su(((const int*)&a4[i])[w], bw[w], acc[i * 8 + j]);
                }
            }
        }

        __syncthreads();                  // all consumers done with stage s
        if (tid == 0 && kt + STAGES < KT) {
            uint32_t ab = smu + SMEM_CTRL + s * STAGE_BYTES;
            MBARRIER_EXPECT_TX(bar, (uint32_t)STAGE_BYTES);
            tma2d(ab,                   &ta, (kt + STAGES) * BK, bm,       bar);
            tma2d(ab + A_BYTES,         &tb, (kt + STAGES) * BK, bn,       bar);
            tma2d(ab + A_BYTES + 16384, &tb, (kt + STAGES) * BK, bn + 128, bar);
        }
    }

    // ---- epilogues: dequant (+GELU); BN=256 divides N -> no guards ----
    if (wid >= 8) {                       // tensor cols 0..127
#pragma unroll
        for (int mi = 0; mi < 4; mi++) {
#pragma unroll
            for (int half = 0; half < 2; half++) {
                int r = bm + warpM * 64 + mi * 16 + (lane >> 2) + half * 8;
                float sa   = __ldg(&sA[r]);
                float fsum = (float)__ldg(&sumA[r]);
                float* Crow = C + (size_t)r * N;
#pragma unroll
                for (int ni = 0; ni < 4; ni++) {
                    int cc = bn + warpN * 32 + ni * 8 + (lane & 3) * 2;
                    float f0 = (float)acc[(mi * 4 + ni) * 4 + half * 2 + 0];
                    float f1 = (float)acc[(mi * 4 + ni) * 4 + half * 2 + 1];
                    float v0 = (sa * __ldg(&sW[cc]))     * (f0 - __ldg(&zp[cc])     * fsum) + __ldg(&bias[cc]);
                    float v1 = (sa * __ldg(&sW[cc + 1])) * (f1 - __ldg(&zp[cc + 1]) * fsum) + __ldg(&bias[cc + 1]);
                    if (DO_GELU) { v0 = gelu_exact(v0); v1 = gelu_exact(v1); }
                    *(float2*)(Crow + cc) = make_float2(v0, v1);
                }
            }
        }
    } else {                              // dp4a cols 128..255: 8 consecutive per thread
        int cbase = bn + 128 + tCol * 8;
#pragma unroll
        for (int i = 0; i < 8; i++) {
            int r = bm + tRow * 8 + i;
            float sa   = __ldg(&sA[r]);
            float fsum = (float)__ldg(&sumA[r]);
            float* Crow = C + (size_t)r * N;
            float o[8];
#pragma unroll
            for (int j = 0; j < 8; j++) {
                int cc = cbase + j;
                float f = (float)acc[i * 8 + j];
                float v = (sa * __ldg(&sW[cc])) * (f - __ldg(&zp[cc]) * fsum) + __ldg(&bias[cc]);
                if (DO_GELU) v = gelu_exact(v);
                o[j] = v;
            }
            *(float4*)(Crow + cbase)     = make_float4(o[0], o[1], o[2], o[3]);
            *(float4*)(Crow + cbase + 4) = make_float4(o[4], o[5], o[6], o[7]);
        }
    }
}

// ---------------- host: tensormap encode via driver entry point ---------------
typedef CUresult (*PFN_encodeTiled)(
    CUtensorMap*, CUtensorMapDataType, cuuint32_t, void*,
    const cuuint64_t*, const cuuint64_t*, const cuuint32_t*, const cuuint32_t*,
    CUtensorMapInterleave, CUtensorMapSwizzle, CUtensorMapL2promotion,
    CUtensorMapFloatOOBfill);

static void make_map_u8(PFN_encodeTiled enc, CUtensorMap* m, const void* ptr,
                        uint64_t rows, uint64_t cols) {
    cuuint64_t dims[2]    = {cols, rows};
    cuuint64_t strides[1] = {cols};
    cuuint32_t box[2]     = {128, 128};
    cuuint32_t es[2]      = {1, 1};
    enc(m, CU_TENSOR_MAP_DATA_TYPE_UINT8, 2, (void*)ptr, dims, strides, box, es,
        CU_TENSOR_MAP_INTERLEAVE_NONE, CU_TENSOR_MAP_SWIZZLE_128B,
        CU_TENSOR_MAP_L2_PROMOTION_L2_128B, CU_TENSOR_MAP_FLOAT_OOB_FILL_NONE);
}

extern "C" void kernel_launch(void* const* d_in, const int* in_sizes, int n_in,
                              void* d_out, int out_size) {
    const float* x    = (const float*)d_in[0];
    const int*   w1q  = (const int*)  d_in[1];
    const float* w1s  = (const float*)d_in[2];
    const float* w1zp = (const float*)d_in[3];
    const float* b1   = (const float*)d_in[4];
    const int*   w2q  = (const int*)  d_in[5];
    const float* w2s  = (const float*)d_in[6];
    const float* w2zp = (const float*)d_in[7];
    const float* b2   = (const float*)d_in[8];
    float* out = (float*)d_out;

    uint8_t *w1u8, *w2u8;
    int8_t *q1, *q2;
    float *g, *s1, *s2;
    int *sum1, *sum2;
    cudaGetSymbolAddress((void**)&w1u8, d_w1u8);
    cudaGetSymbolAddress((void**)&w2u8, d_w2u8);
    cudaGetSymbolAddress((void**)&q1,   d_q1);
    cudaGetSymbolAddress((void**)&q2,   d_q2);
    cudaGetSymbolAddress((void**)&g,    d_g);
    cudaGetSymbolAddress((void**)&s1,   d_s1);
    cudaGetSymbolAddress((void**)&s2,   d_s2);
    cudaGetSymbolAddress((void**)&sum1, d_sum1);
    cudaGetSymbolAddress((void**)&sum2, d_sum2);

    void* fn = nullptr;
    cudaDriverEntryPointQueryResult qr;
    cudaGetDriverEntryPointByVersion("cuTensorMapEncodeTiled", &fn, 12000,
                                     cudaEnableDefault, &qr);
    PFN_encodeTiled enc = (PFN_encodeTiled)fn;

    CUtensorMap tA1, tB1, tA2, tB2;
    make_map_u8(enc, &tA1, q1,   T_DIM, D_DIM);
    make_map_u8(enc, &tB1, w1u8, H_DIM, D_DIM);
    make_map_u8(enc, &tA2, q2,   T_DIM, H_DIM);
    make_map_u8(enc, &tB2, w2u8, D_DIM, H_DIM);

    cudaFuncSetAttribute(gemm_hybrid<true>,
                         cudaFuncAttributeMaxDynamicSharedMemorySize, SMEM_BYTES);
    cudaFuncSetAttribute(gemm_hybrid<false>,
                         cudaFuncAttributeMaxDynamicSharedMemorySize, SMEM_BYTES);

    const int n4 = (int)(((size_t)H_DIM * D_DIM) / 4);
    convert_weights<<<(n4 + 255) / 256, 256>>>(w1q, w1u8, n4);
    convert_weights<<<(n4 + 255) / 256, 256>>>(w2q, w2u8, n4);

    quant_rows<320, 4><<<T_DIM, 320>>>(x, q1, s1, sum1, D_DIM);

    dim3 g1(H_DIM / BN, T_DIM / BM);             // 54 x 64
    gemm_hybrid<true><<<g1, 512, SMEM_BYTES>>>(tA1, tB1, g, D_DIM, H_DIM,
                                               s1, sum1, w1s, w1zp, b1);

    quant_rows<384, 9><<<T_DIM, 384>>>(g, q2, s2, sum2, H_DIM);

    dim3 g2(D_DIM / BN, T_DIM / BM);             // 20 x 64
    gemm_hybrid<false><<<g2, 512, SMEM_BYTES>>>(tA2, tB2, out, H_DIM, D_DIM,
                                                s2, sum2, w2s, w2zp, b2);
}